// round 5
// baseline (speedup 1.0000x reference)
#include <cuda_runtime.h>
#include <cuda_bf16.h>

#define N_NODES 100000
#define N_EDGES 1000000
#define D_FEAT  64

// Neighbor-sum accumulator. Zero-initialized at module load; k_mlp re-zeroes
// its tile after consuming, so every graph replay sees zeros (deterministic).
__device__ float g_agg[N_NODES * D_FEAT];

// ---------------------------------------------------------------------------
// Edge scatter: 16 threads per edge, one float4 chunk each, both directions.
// Coalesced 256B row reads and 256B RED bursts; at the LTS throughput floor.
// ---------------------------------------------------------------------------
__device__ __forceinline__ void red_add_v4(float* addr, float4 v) {
    asm volatile("red.global.add.v4.f32 [%0], {%1, %2, %3, %4};"
                 :: "l"(addr), "f"(v.x), "f"(v.y), "f"(v.z), "f"(v.w)
                 : "memory");
}

__global__ void k_scatter(const float4* __restrict__ X4,
                          const int* __restrict__ ref_a,
                          const int* __restrict__ ref_b) {
    unsigned t = blockIdx.x * blockDim.x + threadIdx.x;
    unsigned e = t >> 4;
    unsigned c = t & 15;
    if (e >= N_EDGES) return;
    int a = __ldg(&ref_a[e]);
    int b = __ldg(&ref_b[e]);
    const int F4 = D_FEAT / 4;   // 16
    float4 xb = __ldg(&X4[(size_t)b * F4 + c]);
    float4 xa = __ldg(&X4[(size_t)a * F4 + c]);
    red_add_v4(&g_agg[((size_t)a * F4 + c) * 4], xb);
    red_add_v4(&g_agg[((size_t)b * F4 + c) * 4], xa);
}

// ---------------------------------------------------------------------------
// Register-fragment TF32 MLP, smem-staged ingress/egress:
//   out = relu(relu((X+agg) @ Wh + bh) @ Wo + bo)
// 256 threads = 8 warps; warp owns 16 rows (m16n8k8, 8 n-tiles).
//   layer-1: phys col 16t+j <-> logical k = t+4j (thread tg owns its quarter)
//   layer-2: layer-1 accumulators ARE the next A fragment (W2 rows permuted).
// Weights packed in fragment order -> one LDS.64 per (s,nt) mma.
// ---------------------------------------------------------------------------
#define TS 68   // tile row stride in words
#define MLP_SMEM ((2 * 4096 + 128 * TS) * 4)   // Wp + Ts = 67584 bytes

__device__ __forceinline__ unsigned f2tf32(float f) {
    unsigned u;
    asm("cvt.rna.tf32.f32 %0, %1;" : "=r"(u) : "f"(f));
    return u;
}

__device__ __forceinline__ void mma_tf32(float* d, unsigned a0, unsigned a1,
                                         unsigned a2, unsigned a3,
                                         unsigned b0, unsigned b1) {
    asm volatile(
        "mma.sync.aligned.m16n8k8.row.col.f32.tf32.tf32.f32 "
        "{%0,%1,%2,%3}, {%4,%5,%6,%7}, {%8,%9}, {%0,%1,%2,%3};\n"
        : "+f"(d[0]), "+f"(d[1]), "+f"(d[2]), "+f"(d[3])
        : "r"(a0), "r"(a1), "r"(a2), "r"(a3), "r"(b0), "r"(b1));
}

__global__ __launch_bounds__(256)
void k_mlp(const float4* __restrict__ agg4, const float4* __restrict__ X4,
           const float* __restrict__ Wh_g, const float* __restrict__ bh,
           const float* __restrict__ Wo_g, const float* __restrict__ bo,
           float4* __restrict__ out4, float4* __restrict__ aggz) {
    extern __shared__ unsigned sm[];
    unsigned* Wp = sm;              // [2][4096] packed weight fragments
    unsigned* Ts = sm + 8192;       // [128][TS] A-tile / output staging

    const int tid  = threadIdx.x;
    const int lane = tid & 31;
    const int warp = tid >> 5;
    const int g    = lane >> 2;      // 0..7
    const int tg   = lane & 3;       // 0..3
    const int row0 = blockIdx.x * 128;

    // ---- Stage weights in fragment-packed order ----
    #pragma unroll
    for (int l = 0; l < 2; l++) {
        const float* W = l ? Wo_g : Wh_g;
        #pragma unroll
        for (int ii = 0; ii < 8; ii++) {
            int i = tid + ii * 256;          // 0..2047
            int ln = i & 31;
            int nt = (i >> 5) & 7;
            int s  = i >> 8;                 // 0..7
            int tgg = ln & 3, gg = ln >> 2;
            // layer 1: fragment k-slot (s, tgg) holds TRUE rows 16*tgg + 2s (+1)
            // layer 2: fragment k-slot (s, tgg) holds TRUE rows 8s + 2*tgg (+1)
            int r = l ? (8 * s + 2 * tgg) : (16 * tgg + 2 * s);
            int n = nt * 8 + gg;
            Wp[l * 4096 + 2 * i]     = f2tf32(__ldg(&W[r * 64 + n]));
            Wp[l * 4096 + 2 * i + 1] = f2tf32(__ldg(&W[(r + 1) * 64 + n]));
        }
    }

    // ---- Coalesced ingress: Ts[r][c] = tf32(X[r] + agg[r]) ----
    #pragma unroll
    for (int i = 0; i < 8; i++) {
        int idx = tid + i * 256;          // 0..2047 float4 in tile
        int r  = idx >> 4;                // 0..127
        int c4 = idx & 15;                // 0..15
        int grow = row0 + r;
        uint4 st = make_uint4(0u, 0u, 0u, 0u);
        if (grow < N_NODES) {
            float4 a = __ldg(&agg4[(size_t)grow * 16 + c4]);
            float4 x = __ldg(&X4[(size_t)grow * 16 + c4]);
            st.x = f2tf32(a.x + x.x);
            st.y = f2tf32(a.y + x.y);
            st.z = f2tf32(a.z + x.z);
            st.w = f2tf32(a.w + x.w);
        }
        *(uint4*)&Ts[r * TS + c4 * 4] = st;
    }
    __syncthreads();

    // ---- Re-zero this block's agg tile, fully coalesced (reads done) ----
    {
        const float4 z4 = make_float4(0.f, 0.f, 0.f, 0.f);
        #pragma unroll
        for (int i = 0; i < 8; i++) {
            int idx = tid + i * 256;
            int grow = row0 + (idx >> 4);
            if (grow < N_NODES)
                aggz[(size_t)grow * 16 + (idx & 15)] = z4;
        }
    }

    // ---- Pull A fragments from smem: 4x LDS.128 per row, own warp region ----
    const int lr0 = warp * 16 + g;       // local tile rows
    const int lr1 = lr0 + 8;
    unsigned a0r[16], a1r[16];           // [j] = phys col 16*tg + j
    #pragma unroll
    for (int q = 0; q < 4; q++) {
        *(uint4*)&a0r[4 * q] = *(const uint4*)&Ts[lr0 * TS + tg * 16 + 4 * q];
        *(uint4*)&a1r[4 * q] = *(const uint4*)&Ts[lr1 * TS + tg * 16 + 4 * q];
    }

    // ================= Layer 1 =================
    float acc[8][4];
    #pragma unroll
    for (int nt = 0; nt < 8; nt++) {
        float blo = __ldg(&bh[nt * 8 + 2 * tg]);
        float bhi = __ldg(&bh[nt * 8 + 2 * tg + 1]);
        acc[nt][0] = blo; acc[nt][1] = bhi; acc[nt][2] = blo; acc[nt][3] = bhi;
    }
    #pragma unroll
    for (int s = 0; s < 8; s++) {
        unsigned A0 = a0r[2 * s], A2 = a0r[2 * s + 1];
        unsigned A1 = a1r[2 * s], A3 = a1r[2 * s + 1];
        #pragma unroll
        for (int nt = 0; nt < 8; nt++) {
            uint2 b = *(const uint2*)&Wp[((s * 8 + nt) * 32 + lane) * 2];
            mma_tf32(acc[nt], A0, A1, A2, A3, b.x, b.y);
        }
    }

    // ---- relu + cvt: accumulators become layer-2 A fragments directly ----
    unsigned h0[8], h1[8], h2[8], h3[8];
    #pragma unroll
    for (int s = 0; s < 8; s++) {
        h0[s] = f2tf32(fmaxf(acc[s][0], 0.f));   // row g,   col 8s+2tg
        h1[s] = f2tf32(fmaxf(acc[s][2], 0.f));   // row g+8, col 8s+2tg
        h2[s] = f2tf32(fmaxf(acc[s][1], 0.f));   // row g,   col 8s+2tg+1
        h3[s] = f2tf32(fmaxf(acc[s][3], 0.f));   // row g+8, col 8s+2tg+1
    }

    // ================= Layer 2 =================
    #pragma unroll
    for (int nt = 0; nt < 8; nt++) {
        float blo = __ldg(&bo[nt * 8 + 2 * tg]);
        float bhi = __ldg(&bo[nt * 8 + 2 * tg + 1]);
        acc[nt][0] = blo; acc[nt][1] = bhi; acc[nt][2] = blo; acc[nt][3] = bhi;
    }
    #pragma unroll
    for (int s = 0; s < 8; s++) {
        #pragma unroll
        for (int nt = 0; nt < 8; nt++) {
            uint2 b = *(const uint2*)&Wp[4096 + ((s * 8 + nt) * 32 + lane) * 2];
            mma_tf32(acc[nt], h0[s], h1[s], h2[s], h3[s], b.x, b.y);
        }
    }

    // ---- Egress: stage relu(out) into own warp's smem stripe ----
    // (Each warp writes only rows [16*warp, 16*warp+16) which only it read
    //  during fragment load, so no barrier needed before these stores.)
    #pragma unroll
    for (int nt = 0; nt < 8; nt++) {
        int c = nt * 8 + 2 * tg;
        *(uint2*)&Ts[lr0 * TS + c] = make_uint2(
            __float_as_uint(fmaxf(acc[nt][0], 0.f)),
            __float_as_uint(fmaxf(acc[nt][1], 0.f)));
        *(uint2*)&Ts[lr1 * TS + c] = make_uint2(
            __float_as_uint(fmaxf(acc[nt][2], 0.f)),
            __float_as_uint(fmaxf(acc[nt][3], 0.f)));
    }
    __syncthreads();

    // ---- Coalesced STG.128 of the output tile ----
    #pragma unroll
    for (int i = 0; i < 8; i++) {
        int idx = tid + i * 256;
        int r  = idx >> 4;
        int c4 = idx & 15;
        int grow = row0 + r;
        if (grow < N_NODES) {
            uint4 v = *(const uint4*)&Ts[r * TS + c4 * 4];
            out4[(size_t)grow * 16 + c4] = make_float4(
                __uint_as_float(v.x), __uint_as_float(v.y),
                __uint_as_float(v.z), __uint_as_float(v.w));
        }
    }
}

// ---------------------------------------------------------------------------
// Inputs: 0=X, 1=ref_a, 2=ref_b, 3=v_map(unused), 4=v_count(unused),
//         5=W_hidden, 6=b_hidden, 7=W_out, 8=b_out
// ---------------------------------------------------------------------------
extern "C" void kernel_launch(void* const* d_in, const int* in_sizes, int n_in,
                              void* d_out, int out_size) {
    const float* X   = (const float*)d_in[0];
    const int* ref_a = (const int*)d_in[1];
    const int* ref_b = (const int*)d_in[2];
    const float* Wh  = (const float*)d_in[5];
    const float* bh  = (const float*)d_in[6];
    const float* Wo  = (const float*)d_in[7];
    const float* bo  = (const float*)d_in[8];
    float* out = (float*)d_out;

    float* agg;
    cudaGetSymbolAddress((void**)&agg, g_agg);

    // 1) edge scatter into zeroed agg (zero-invariant maintained by k_mlp)
    {
        long long total = (long long)N_EDGES * 16;
        int blocks = (int)((total + 255) / 256);
        k_scatter<<<blocks, 256>>>((const float4*)X, ref_a, ref_b);
    }

    // 2) register-fragment TF32 MLP (adds X, consumes agg, re-zeroes agg)
    {
        cudaFuncSetAttribute(k_mlp, cudaFuncAttributeMaxDynamicSharedMemorySize,
                             MLP_SMEM);
        int blocks = (N_NODES + 127) / 128;   // 782
        k_mlp<<<blocks, 256, MLP_SMEM>>>((const float4*)agg, (const float4*)X,
                                         Wh, bh, Wo, bo, (float4*)out,
                                         (float4*)agg);
    }
}